// round 1
// baseline (speedup 1.0000x reference)
#include <cuda_runtime.h>
#include <cuda_bf16.h>
#include <cstdint>

// ---------------------------------------------------------------------------
// SplitLinear: y[m, n*410+f] = u[m,f] + sx[m,n]*G[f,n] + c[f]   (first 4096 cols)
//   u  = X @ Wfc^T           (M x 410)
//   sx = X @ Wsel^T + bsel   (M x 10)   -> computed as columns 410..419 of GEMM
//   G  = Wfc @ Wexp          (410 x 10)
//   c  = Wfc @ bexp + bfc    (410)
// ---------------------------------------------------------------------------

#define KDIM   4096
#define NFC    410
#define NCOLS  420      // 410 fc columns + 10 selector columns
#define USTRIDE 432     // padded row stride of U scratch
#define MMAX   4096

#define BM 128
#define BN 128
#define BK 32
#define SST 136                 // smem row stride (conflict-free: bank = 8k+m)
#define BUFSZ (BK * SST)        // uint32 elems per buffer

__device__ float g_U[MMAX * USTRIDE];   // GEMM scratch (u and raw sx)
__device__ float g_G[10 * 416];         // G[n][f], padded
__device__ float g_c[416];              // c[f]

// ---------------------------------------------------------------------------
// prep: G[f,n] = sum_i Wfc[f,i]*Wexp[i,n];  c[f] = sum_i Wfc[f,i]*bexp[i] + bfc[f]
// ---------------------------------------------------------------------------
__global__ void prep_kernel(const float* __restrict__ Wfc, const float* __restrict__ Wexp,
                            const float* __restrict__ bexp, const float* __restrict__ bfc) {
    int f = blockIdx.x;                      // 0..409
    const float* wrow = Wfc + (size_t)f * KDIM;
    float acc[11];
#pragma unroll
    for (int v = 0; v < 11; v++) acc[v] = 0.f;
    for (int k = threadIdx.x; k < KDIM; k += 256) {
        float w = wrow[k];
        const float* we = Wexp + (size_t)k * 10;
#pragma unroll
        for (int n = 0; n < 10; n++) acc[n] += w * we[n];
        acc[10] += w * bexp[k];
    }
    __shared__ float red[8][11];
    int lane = threadIdx.x & 31, warp = threadIdx.x >> 5;
#pragma unroll
    for (int v = 0; v < 11; v++) {
        float s = acc[v];
#pragma unroll
        for (int o = 16; o; o >>= 1) s += __shfl_xor_sync(0xffffffffu, s, o);
        if (lane == 0) red[warp][v] = s;
    }
    __syncthreads();
    if (threadIdx.x < 11) {
        float s = 0.f;
#pragma unroll
        for (int w = 0; w < 8; w++) s += red[w][threadIdx.x];
        if (threadIdx.x < 10) g_G[threadIdx.x * 416 + f] = s;
        else                  g_c[f] = s + bfc[f];
    }
}

// ---------------------------------------------------------------------------
// tf32 GEMM: U[m, col] = sum_k X[m,k] * B[col,k]
//   B[col] = Wfc[col] for col<410, Wsel[col-410] for 410<=col<420, 0 beyond.
// ---------------------------------------------------------------------------
__device__ __forceinline__ uint32_t f2tf(float f) {
    uint32_t r;
    asm("cvt.rna.tf32.f32 %0, %1;" : "=r"(r) : "f"(f));
    return r;
}

__device__ __forceinline__ void mma8(float* c, const uint32_t* a, const uint32_t* b) {
    asm volatile(
        "mma.sync.aligned.m16n8k8.row.col.f32.tf32.tf32.f32 "
        "{%0,%1,%2,%3}, {%4,%5,%6,%7}, {%8,%9}, {%0,%1,%2,%3};"
        : "+f"(c[0]), "+f"(c[1]), "+f"(c[2]), "+f"(c[3])
        : "r"(a[0]), "r"(a[1]), "r"(a[2]), "r"(a[3]), "r"(b[0]), "r"(b[1]));
}

__global__ __launch_bounds__(256, 1)
void gemm_kernel(const float* __restrict__ x, const float* __restrict__ Wfc,
                 const float* __restrict__ Wsel) {
    extern __shared__ uint32_t sm[];
    uint32_t* As = sm;              // 2 buffers of BK x SST (tf32, k-major rows)
    uint32_t* Bs = sm + 2 * BUFSZ;  // 2 buffers

    const int tid  = threadIdx.x;
    const int lane = tid & 31;
    const int warp = tid >> 5;
    const int wm   = warp >> 2;     // 0..1  (64-row warp tiles)
    const int wn   = warp & 3;      // 0..3  (32-col warp tiles)
    const int gid  = lane >> 2;     // 0..7
    const int tig  = lane & 3;      // 0..3
    const int m0   = blockIdx.y * BM;
    const int n0   = blockIdx.x * BN;

    // loader coords: thread owns row lr, k-chunks {lk0, lk0+2, lk0+4, lk0+6} (float4)
    const int lr  = tid & 127;
    const int lk0 = tid >> 7;       // 0/1

    const float* asrc = x + (size_t)(m0 + lr) * KDIM;
    int bcol = n0 + lr;
    const float* bsrc = Wfc;
    bool bvalid = true;
    if (bcol < NFC)        bsrc = Wfc + (size_t)bcol * KDIM;
    else if (bcol < NCOLS) bsrc = Wsel + (size_t)(bcol - NFC) * KDIM;
    else                   bvalid = false;

    float4 av[4], bv[4];
    float acc[4][4][4];
#pragma unroll
    for (int mi = 0; mi < 4; mi++)
#pragma unroll
        for (int ni = 0; ni < 4; ni++)
#pragma unroll
            for (int q = 0; q < 4; q++) acc[mi][ni][q] = 0.f;

    auto load_g = [&](int kt) {
        int kb = kt * BK;
#pragma unroll
        for (int i = 0; i < 4; i++) {
            int kc = lk0 + 2 * i;
            av[i] = *reinterpret_cast<const float4*>(asrc + kb + kc * 4);
            if (bvalid) bv[i] = *reinterpret_cast<const float4*>(bsrc + kb + kc * 4);
            else        bv[i] = make_float4(0.f, 0.f, 0.f, 0.f);
        }
    };
    auto store_s = [&](int buf) {
        uint32_t* Ad = As + buf * BUFSZ;
        uint32_t* Bd = Bs + buf * BUFSZ;
#pragma unroll
        for (int i = 0; i < 4; i++) {
            int kc = lk0 + 2 * i;
            const float* afp = reinterpret_cast<const float*>(&av[i]);
            const float* bfp = reinterpret_cast<const float*>(&bv[i]);
#pragma unroll
            for (int j = 0; j < 4; j++) {
                Ad[(kc * 4 + j) * SST + lr] = f2tf(afp[j]);
                Bd[(kc * 4 + j) * SST + lr] = f2tf(bfp[j]);
            }
        }
    };

    load_g(0);
    store_s(0);
    __syncthreads();

    const int NKT = KDIM / BK;   // 128
    int cur = 0;
    for (int kt = 0; kt < NKT; kt++) {
        if (kt + 1 < NKT) load_g(kt + 1);

        const uint32_t* Ac = As + cur * BUFSZ;
        const uint32_t* Bc = Bs + cur * BUFSZ;
#pragma unroll
        for (int ks = 0; ks < 4; ks++) {
            int k0 = ks * 8 + tig;
            uint32_t a[4][4], b[4][2];
#pragma unroll
            for (int mi = 0; mi < 4; mi++) {
                int r = wm * 64 + mi * 16 + gid;
                a[mi][0] = Ac[k0 * SST + r];
                a[mi][1] = Ac[k0 * SST + r + 8];
                a[mi][2] = Ac[(k0 + 4) * SST + r];
                a[mi][3] = Ac[(k0 + 4) * SST + r + 8];
            }
#pragma unroll
            for (int ni = 0; ni < 4; ni++) {
                int cc = wn * 32 + ni * 8 + gid;
                b[ni][0] = Bc[k0 * SST + cc];
                b[ni][1] = Bc[(k0 + 4) * SST + cc];
            }
#pragma unroll
            for (int mi = 0; mi < 4; mi++)
#pragma unroll
                for (int ni = 0; ni < 4; ni++)
                    mma8(acc[mi][ni], a[mi], b[ni]);
        }

        if (kt + 1 < NKT) {
            store_s(cur ^ 1);
            __syncthreads();
            cur ^= 1;
        }
    }

    // write U (only real columns < 420)
#pragma unroll
    for (int mi = 0; mi < 4; mi++) {
        int r0 = m0 + wm * 64 + mi * 16 + gid;
#pragma unroll
        for (int ni = 0; ni < 4; ni++) {
            int col = n0 + wn * 32 + ni * 8 + 2 * tig;
            if (col < NCOLS) {
                g_U[(size_t)r0 * USTRIDE + col]           = acc[mi][ni][0];
                g_U[(size_t)r0 * USTRIDE + col + 1]       = acc[mi][ni][1];
                g_U[(size_t)(r0 + 8) * USTRIDE + col]     = acc[mi][ni][2];
                g_U[(size_t)(r0 + 8) * USTRIDE + col + 1] = acc[mi][ni][3];
            }
        }
    }
}

// ---------------------------------------------------------------------------
// epilogue: out[m, j] = u[m,f] + sx[m,n]*G[n,f] + c[f],  n=j/410, f=j-410n
// ---------------------------------------------------------------------------
__global__ void epi_kernel(const float* __restrict__ bsel, float* __restrict__ out) {
    int m = blockIdx.x;
    __shared__ float sx[10];
    if (threadIdx.x < 10)
        sx[threadIdx.x] = g_U[(size_t)m * USTRIDE + NFC + threadIdx.x] + bsel[threadIdx.x];
    __syncthreads();
    const float* Ur = g_U + (size_t)m * USTRIDE;
    float* orow = out + (size_t)m * 4096;
    for (int j = threadIdx.x; j < 4096; j += 256) {
        int n = j / NFC;
        int f = j - n * NFC;
        orow[j] = Ur[f] + sx[n] * g_G[n * 416 + f] + g_c[f];
    }
}

// ---------------------------------------------------------------------------
extern "C" void kernel_launch(void* const* d_in, const int* in_sizes, int n_in,
                              void* d_out, int out_size) {
    const float* x    = (const float*)d_in[0];
    const float* Wsel = (const float*)d_in[1];
    const float* bsel = (const float*)d_in[2];
    const float* Wexp = (const float*)d_in[3];
    const float* bexp = (const float*)d_in[4];
    const float* Wfc  = (const float*)d_in[5];
    const float* bfc  = (const float*)d_in[6];
    float* out = (float*)d_out;

    int M = in_sizes[0] / KDIM;   // 4096 tokens (2 x 2048)

    const int smem_bytes = 4 * BUFSZ * 4;   // 69632
    cudaFuncSetAttribute(gemm_kernel, cudaFuncAttributeMaxDynamicSharedMemorySize, smem_bytes);

    prep_kernel<<<NFC, 256>>>(Wfc, Wexp, bexp, bfc);
    dim3 grid(BN == 128 ? 4 : (NCOLS + BN - 1) / BN, M / BM);
    gemm_kernel<<<grid, 256, smem_bytes>>>(x, Wfc, Wsel);
    epi_kernel<<<M, 256>>>(bsel, out);
}

// round 3
// speedup vs baseline: 1.6637x; 1.6637x over previous
#include <cuda_runtime.h>
#include <cuda_bf16.h>
#include <cstdint>

// ---------------------------------------------------------------------------
// y[m, n*410+f] = u[m,f] + sx[m,n]*G[n,f] + c[f]
//   U[:, 0:410] = X @ Wfc^T,  U[:, 410:420] = X @ Wsel^T  (one tf32 GEMM)
//   G = Wfc @ Wexp, c = Wfc @ bexp + bfc
// GEMM: mma.sync m16n8k8 tf32 (legacy HMMA; tcgen05 not available: harness
// emits compute_103 PTX, no sm_103a target), cp.async 4-stage pipeline,
// ldmatrix fragment loads, read-side cvt.rna.tf32.
// ---------------------------------------------------------------------------

#define KDIM    4096
#define NFC     410
#define NCOLS   420
#define USTRIDE 432
#define MMAX    4096

#define BM 128
#define BN 128
#define BK 32
#define NKT (KDIM / BK)              // 128
#define STAGES 4
#define TILE_BYTES  (BM * BK * 4)    // 16384 (A tile; B tile same)
#define STAGE_BYTES (2 * TILE_BYTES) // 32768

__device__ float g_U[MMAX * USTRIDE];
__device__ float g_G[10 * 416];
__device__ float g_c[416];

// ---------------- helpers ----------------------------------------------------
__device__ __forceinline__ uint32_t smem_u32(const void* p) {
    uint32_t a;
    asm("{ .reg .u64 t; cvta.to.shared.u64 t, %1; cvt.u32.u64 %0, t; }" : "=r"(a) : "l"(p));
    return a;
}
#define SW128(x) ((x) ^ (((x) >> 3) & 0x70))

__device__ __forceinline__ void cp16(uint32_t dst, const void* src, uint32_t srcsize) {
    asm volatile("cp.async.cg.shared.global [%0], [%1], 16, %2;"
                 :: "r"(dst), "l"(src), "r"(srcsize) : "memory");
}
__device__ __forceinline__ void cp_commit() {
    asm volatile("cp.async.commit_group;" ::: "memory");
}
__device__ __forceinline__ void cp_wait2() {
    asm volatile("cp.async.wait_group 2;" ::: "memory");
}
__device__ __forceinline__ void ldsm4(uint32_t* r, uint32_t a) {
    asm volatile("ldmatrix.sync.aligned.m8n8.x4.shared.b16 {%0,%1,%2,%3}, [%4];"
                 : "=r"(r[0]), "=r"(r[1]), "=r"(r[2]), "=r"(r[3]) : "r"(a));
}
__device__ __forceinline__ uint32_t f2tf(uint32_t v) {
    uint32_t r;
    asm("cvt.rna.tf32.f32 %0, %1;" : "=r"(r) : "f"(__uint_as_float(v)));
    return r;
}
__device__ __forceinline__ void mma8(float* c, const uint32_t* a, const uint32_t* b) {
    asm volatile(
        "mma.sync.aligned.m16n8k8.row.col.f32.tf32.tf32.f32 "
        "{%0,%1,%2,%3}, {%4,%5,%6,%7}, {%8,%9}, {%0,%1,%2,%3};"
        : "+f"(c[0]), "+f"(c[1]), "+f"(c[2]), "+f"(c[3])
        : "r"(a[0]), "r"(a[1]), "r"(a[2]), "r"(a[3]), "r"(b[0]), "r"(b[1]));
}

// ---------------------------------------------------------------------------
// prep: G[n,f] = sum_i Wfc[f,i]*Wexp[i,n];  c[f] = sum_i Wfc[f,i]*bexp[i]+bfc[f]
// ---------------------------------------------------------------------------
__global__ void prep_kernel(const float* __restrict__ Wfc, const float* __restrict__ Wexp,
                            const float* __restrict__ bexp, const float* __restrict__ bfc) {
    __shared__ float swe[2560];
    __shared__ float sbe[256];
    __shared__ float red[8][11];
    int f = blockIdx.x;
    const float* wrow = Wfc + (size_t)f * KDIM;
    float acc[11];
#pragma unroll
    for (int v = 0; v < 11; v++) acc[v] = 0.f;

    for (int ch = 0; ch < KDIM / 256; ch++) {
        int base = ch * 256;
        for (int i = threadIdx.x; i < 2560; i += 256) swe[i] = Wexp[(size_t)base * 10 + i];
        sbe[threadIdx.x] = bexp[base + threadIdx.x];
        __syncthreads();
        float w = wrow[base + threadIdx.x];
#pragma unroll
        for (int n = 0; n < 10; n++) acc[n] += w * swe[threadIdx.x * 10 + n];
        acc[10] += w * sbe[threadIdx.x];
        __syncthreads();
    }
    int lane = threadIdx.x & 31, warp = threadIdx.x >> 5;
#pragma unroll
    for (int v = 0; v < 11; v++) {
        float s = acc[v];
#pragma unroll
        for (int o = 16; o; o >>= 1) s += __shfl_xor_sync(0xffffffffu, s, o);
        if (lane == 0) red[warp][v] = s;
    }
    __syncthreads();
    if (threadIdx.x < 11) {
        float s = 0.f;
#pragma unroll
        for (int w = 0; w < 8; w++) s += red[w][threadIdx.x];
        if (threadIdx.x < 10) g_G[threadIdx.x * 416 + f] = s;
        else                  g_c[f] = s + bfc[f];
    }
}

// ---------------------------------------------------------------------------
// GEMM: 128x128 block, 4 warps (2x2) of 64x64, cp.async pipeline
// ---------------------------------------------------------------------------
__global__ __launch_bounds__(128, 1)
void gemm_kernel(const float* __restrict__ x, const float* __restrict__ Wfc,
                 const float* __restrict__ Wsel) {
    extern __shared__ char dyn[];
    char* bufs = (char*)(((uintptr_t)dyn + 1023) & ~(uintptr_t)1023);
    const uint32_t bufs_u32 = smem_u32(bufs);

    const int tid  = threadIdx.x;
    const int lane = tid & 31;
    const int warp = tid >> 5;
    const int wm   = warp >> 1;        // 0..1
    const int wn   = warp & 1;         // 0..1
    const int m0   = blockIdx.y * BM;
    const int n0   = blockIdx.x * BN;

    // ---- loader setup: thread owns rows {lrow + 16i}, 16B chunk lq ----
    const int lrow = tid >> 3;         // 0..15
    const int lq   = tid & 7;          // 0..7
    const uint32_t dstoff = (uint32_t)(lrow * 128 + ((lq * 16) ^ ((lrow & 7) << 4)));
    const char* aglob = (const char*)(x + (size_t)(m0 + lrow) * KDIM + lq * 4);

    const char* bptr[8];
    uint32_t    bsz[8];
#pragma unroll
    for (int i = 0; i < 8; i++) {
        int bc = n0 + i * 16 + lrow;
        if (bc < NFC)        { bptr[i] = (const char*)(Wfc  + (size_t)bc * KDIM + lq * 4); bsz[i] = 16; }
        else if (bc < NCOLS) { bptr[i] = (const char*)(Wsel + (size_t)(bc - NFC) * KDIM + lq * 4); bsz[i] = 16; }
        else                 { bptr[i] = (const char*)Wfc; bsz[i] = 0; }
    }

    auto issue = [&](int kt) {
        int stage = kt & (STAGES - 1);
        uint32_t ad = bufs_u32 + stage * STAGE_BYTES + dstoff;
        uint32_t bd = ad + TILE_BYTES;
        const char* as = aglob + (size_t)kt * 128;
#pragma unroll
        for (int i = 0; i < 8; i++)
            cp16(ad + i * 2048, as + (size_t)i * (16 * KDIM * 4), 16);
#pragma unroll
        for (int i = 0; i < 8; i++)
            cp16(bd + i * 2048, bptr[i] + (size_t)kt * 128, bsz[i]);
    };

    // ---- fragment address constants (per lane) ----
    const uint32_t aoff = (uint32_t)((wm * 64 + (lane & 15)) * 128);
    const uint32_t xA   = (uint32_t)((lane & 7) << 4);
    const uint32_t hA   = (lane & 16) ? 16u : 0u;
    const uint32_t boff = (uint32_t)((wn * 64 + (lane & 7) + ((lane & 16) ? 8 : 0)) * 128);
    const uint32_t xB   = xA;
    const uint32_t hB   = (lane & 8) ? 16u : 0u;

    float acc[4][8][4];
#pragma unroll
    for (int mi = 0; mi < 4; mi++)
#pragma unroll
        for (int nj = 0; nj < 8; nj++)
#pragma unroll
            for (int q = 0; q < 4; q++) acc[mi][nj][q] = 0.f;

    // prologue: fill 3 stages
    issue(0); cp_commit();
    issue(1); cp_commit();
    issue(2); cp_commit();

#pragma unroll 1
    for (int kt = 0; kt < NKT; kt++) {
        cp_wait2();
        __syncthreads();
        if (kt + 3 < NKT) issue(kt + 3);
        cp_commit();

        const uint32_t As = bufs_u32 + (kt & (STAGES - 1)) * STAGE_BYTES;
        const uint32_t Bs = As + TILE_BYTES;
#pragma unroll
        for (int ks = 0; ks < 4; ks++) {
            const uint32_t ka = (uint32_t)(ks * 32 + hA) ^ xA;
            const uint32_t kb = (uint32_t)(ks * 32 + hB) ^ xB;
            uint32_t a[4][4], b[4][4];
#pragma unroll
            for (int mi = 0; mi < 4; mi++) {
                ldsm4(a[mi], As + aoff + mi * 2048 + ka);
            }
#pragma unroll
            for (int p = 0; p < 4; p++) {
                ldsm4(b[p], Bs + boff + p * 2048 + kb);
            }
#pragma unroll
            for (int mi = 0; mi < 4; mi++)
#pragma unroll
                for (int q = 0; q < 4; q++) a[mi][q] = f2tf(a[mi][q]);
#pragma unroll
            for (int p = 0; p < 4; p++)
#pragma unroll
                for (int q = 0; q < 4; q++) b[p][q] = f2tf(b[p][q]);
#pragma unroll
            for (int mi = 0; mi < 4; mi++)
#pragma unroll
                for (int p = 0; p < 4; p++) {
                    mma8(acc[mi][2 * p],     a[mi], &b[p][0]);
                    mma8(acc[mi][2 * p + 1], a[mi], &b[p][2]);
                }
        }
    }

    // ---- write U directly (guard pad columns) ----
    const int gid = lane >> 2;
    const int tig = lane & 3;
#pragma unroll
    for (int mi = 0; mi < 4; mi++) {
        int r0 = m0 + wm * 64 + mi * 16 + gid;
#pragma unroll
        for (int nj = 0; nj < 8; nj++) {
            int col = n0 + wn * 64 + nj * 8 + 2 * tig;
            if (col < NCOLS) {
                float2 v0 = make_float2(acc[mi][nj][0], acc[mi][nj][1]);
                float2 v1 = make_float2(acc[mi][nj][2], acc[mi][nj][3]);
                *reinterpret_cast<float2*>(&g_U[(size_t)r0 * USTRIDE + col])       = v0;
                *reinterpret_cast<float2*>(&g_U[(size_t)(r0 + 8) * USTRIDE + col]) = v1;
            }
        }
    }
}

// ---------------------------------------------------------------------------
// epilogue: out[m, j] = u[m,f] + sx[m,n]*G[n,f] + c[f]
// ---------------------------------------------------------------------------
__global__ void epi_kernel(const float* __restrict__ bsel, float* __restrict__ out) {
    int m = blockIdx.x;
    __shared__ float sx[10];
    if (threadIdx.x < 10)
        sx[threadIdx.x] = g_U[(size_t)m * USTRIDE + NFC + threadIdx.x] + bsel[threadIdx.x];
    __syncthreads();
    const float* Ur = g_U + (size_t)m * USTRIDE;
    float* orow = out + (size_t)m * 4096;
    for (int j = threadIdx.x; j < 4096; j += 256) {
        int n = j / NFC;
        int f = j - n * NFC;
        orow[j] = Ur[f] + sx[n] * g_G[n * 416 + f] + g_c[f];
    }
}

// ---------------------------------------------------------------------------
extern "C" void kernel_launch(void* const* d_in, const int* in_sizes, int n_in,
                              void* d_out, int out_size) {
    const float* x    = (const float*)d_in[0];
    const float* Wsel = (const float*)d_in[1];
    const float* bsel = (const float*)d_in[2];
    const float* Wexp = (const float*)d_in[3];
    const float* bexp = (const float*)d_in[4];
    const float* Wfc  = (const float*)d_in[5];
    const float* bfc  = (const float*)d_in[6];
    float* out = (float*)d_out;

    int M = in_sizes[0] / KDIM;   // 4096

    const int smem_bytes = STAGES * STAGE_BYTES + 1024;   // 132096
    cudaFuncSetAttribute(gemm_kernel, cudaFuncAttributeMaxDynamicSharedMemorySize, smem_bytes);

    prep_kernel<<<NFC, 256>>>(Wfc, Wexp, bexp, bfc);
    dim3 grid((NCOLS + BN - 1) / BN, M / BM);   // (4, 32)
    gemm_kernel<<<grid, 128, smem_bytes>>>(x, Wfc, Wsel);
    epi_kernel<<<M, 256>>>(bsel, out);
}